// round 1
// baseline (speedup 1.0000x reference)
#include <cuda_runtime.h>
#include <math.h>

// Problem constants (from reference setup_inputs: G=2048, CROPS=4, D=128)
#define N_ROWS 8192
#define DIM    128
#define BM     128          // i-rows per CTA
#define JTILE  128          // j-cols per inner tile
#define JCHUNKS 8           // j split across grid.y (deterministic partials, no atomics)
#define KC     32           // k-chunk kept in smem
#define KP     34           // padded k width (conflict-free, float2-aligned)

#define EXP2_SCALE 2.8853900817779268f   // 1/(tau*ln2), tau=0.5
#define EXP_SELF   7.38905609893065f     // exp(1/tau) = e^2

// Scratch (device globals — no allocation in kernel_launch)
__device__ float g_z[N_ROWS * DIM];                 // normalized features
__device__ float g_Spart[JCHUNKS][N_ROWS];          // per-chunk partial row sums of exp
__device__ float g_part[N_ROWS / 8];                // per-CTA partial losses

// ---------------------------------------------------------------------------
// Kernel A: row-normalize features (one warp per row)
// ---------------------------------------------------------------------------
__global__ void k_normalize(const float* __restrict__ f, int n) {
    int warp = (blockIdx.x * blockDim.x + threadIdx.x) >> 5;
    int lane = threadIdx.x & 31;
    if (warp >= n) return;
    const float* row = f + (size_t)warp * DIM;
    float v0 = row[lane];
    float v1 = row[lane + 32];
    float v2 = row[lane + 64];
    float v3 = row[lane + 96];
    float ss = v0 * v0 + v1 * v1 + v2 * v2 + v3 * v3;
    #pragma unroll
    for (int o = 16; o; o >>= 1) ss += __shfl_xor_sync(0xffffffffu, ss, o);
    float nrm = sqrtf(ss);
    float inv = 1.0f / fmaxf(nrm, 1e-8f);
    float* z = g_z + (size_t)warp * DIM;
    z[lane]      = v0 * inv;
    z[lane + 32] = v1 * inv;
    z[lane + 64] = v2 * inv;
    z[lane + 96] = v3 * inv;
}

// ---------------------------------------------------------------------------
// Kernel B: fused tile-GEMM -> exp -> row-sum partials.
// CTA = 256 threads (16x16), 8x8 accumulator micro-tile per thread.
// grid = (n/BM, JCHUNKS). Each CTA owns 128 i-rows x (n/JCHUNKS) j-cols.
// ---------------------------------------------------------------------------
__global__ void __launch_bounds__(256) k_scores(int n) {
    __shared__ float zi[BM * KP];
    __shared__ float zj[JTILE * KP];

    const int i0 = blockIdx.x * BM;
    const int j0 = blockIdx.y * (n / JCHUNKS);
    const int t  = threadIdx.x;
    const int tx = t & 15;
    const int ty = t >> 4;

    float rowAcc[8];
    #pragma unroll
    for (int ii = 0; ii < 8; ii++) rowAcc[ii] = 0.0f;

    const int jspan = n / JCHUNKS;   // 1024
    for (int jb = 0; jb < jspan; jb += JTILE) {
        float acc[8][8];
        #pragma unroll
        for (int ii = 0; ii < 8; ii++)
            #pragma unroll
            for (int jj = 0; jj < 8; jj++) acc[ii][jj] = 0.0f;

        for (int kb = 0; kb < DIM; kb += KC) {
            __syncthreads();   // previous readers done before overwrite
            // load 128x32 of zi and zj (16 elems each per thread, coalesced)
            #pragma unroll
            for (int idx = t; idx < BM * KC; idx += 256) {
                int r = idx >> 5;        // /KC
                int c = idx & 31;        // %KC
                zi[r * KP + c] = g_z[(size_t)(i0 + r) * DIM + kb + c];
                zj[r * KP + c] = g_z[(size_t)(j0 + jb + r) * DIM + kb + c];
            }
            __syncthreads();

            #pragma unroll 4
            for (int k2 = 0; k2 < KC; k2 += 2) {
                float2 af[8], bf[8];
                #pragma unroll
                for (int ii = 0; ii < 8; ii++)
                    af[ii] = *(const float2*)&zi[(ty + ii * 16) * KP + k2];
                #pragma unroll
                for (int jj = 0; jj < 8; jj++)
                    bf[jj] = *(const float2*)&zj[(tx + jj * 16) * KP + k2];
                #pragma unroll
                for (int ii = 0; ii < 8; ii++)
                    #pragma unroll
                    for (int jj = 0; jj < 8; jj++) {
                        acc[ii][jj] = fmaf(af[ii].x, bf[jj].x, acc[ii][jj]);
                        acc[ii][jj] = fmaf(af[ii].y, bf[jj].y, acc[ii][jj]);
                    }
            }
        }

        // epilogue: exp and accumulate into per-thread row sums
        #pragma unroll
        for (int ii = 0; ii < 8; ii++) {
            float s = 0.0f;
            #pragma unroll
            for (int jj = 0; jj < 8; jj++)
                s += exp2f(acc[ii][jj] * EXP2_SCALE);
            rowAcc[ii] += s;
        }
    }

    // reduce the 16 tx-lanes per row (deterministic, fixed order)
    __syncthreads();
    float* sred = zi;   // reuse: 128 rows x 16 = 2048 floats < BM*KP
    #pragma unroll
    for (int ii = 0; ii < 8; ii++)
        sred[(ty + ii * 16) * 16 + tx] = rowAcc[ii];
    __syncthreads();
    if (t < BM) {
        float s = 0.0f;
        #pragma unroll
        for (int u = 0; u < 16; u++) s += sred[t * 16 + u];
        g_Spart[blockIdx.y][i0 + t] = s;
    }
}

// ---------------------------------------------------------------------------
// Kernel C: per-row group sum P_i (4 dots), combine with S_i, per-row loss,
// per-CTA partial sum. One warp per row, 8 rows per CTA.
// ---------------------------------------------------------------------------
__global__ void k_rowloss(int n, int cr) {
    __shared__ float tvals[8];
    int row  = blockIdx.x * 8 + (threadIdx.x >> 5);
    int lane = threadIdx.x & 31;
    float tv = 0.0f;
    if (row < n) {
        const float* zr = g_z + (size_t)row * DIM;
        float a0 = zr[lane], a1 = zr[lane + 32], a2 = zr[lane + 64], a3 = zr[lane + 96];
        int gb = (row / cr) * cr;
        float P = 0.0f;
        for (int jj = 0; jj < cr; jj++) {
            const float* zc = g_z + (size_t)(gb + jj) * DIM;
            float d = a0 * zc[lane] + a1 * zc[lane + 32] + a2 * zc[lane + 64] + a3 * zc[lane + 96];
            #pragma unroll
            for (int o = 16; o; o >>= 1) d += __shfl_xor_sync(0xffffffffu, d, o);
            P += exp2f(d * EXP2_SCALE);
        }
        float S = 0.0f;
        #pragma unroll
        for (int c = 0; c < JCHUNKS; c++) S += g_Spart[c][row];
        float pos = P - EXP_SELF;   // remove exact self term exp(1/tau)
        float neg = S - P;
        tv = logf(neg) - logf(pos); // = -log(pos/neg)
    }
    if (lane == 0) tvals[threadIdx.x >> 5] = tv;
    __syncthreads();
    if (threadIdx.x == 0) {
        float s = 0.0f;
        #pragma unroll
        for (int u = 0; u < 8; u++) s += tvals[u];
        g_part[blockIdx.x] = s;
    }
}

// ---------------------------------------------------------------------------
// Kernel D: deterministic final reduction -> d_out[0] = mean
// ---------------------------------------------------------------------------
__global__ void k_reduce(float* __restrict__ out, int n) {
    __shared__ float sm[256];
    int t = threadIdx.x;
    int m = n / 8;
    float s = 0.0f;
    for (int idx = t; idx < m; idx += 256) s += g_part[idx];
    sm[t] = s;
    __syncthreads();
    #pragma unroll
    for (int off = 128; off; off >>= 1) {
        if (t < off) sm[t] += sm[t + off];
        __syncthreads();
    }
    if (t == 0) out[0] = sm[0] / (float)n;
}

// ---------------------------------------------------------------------------
extern "C" void kernel_launch(void* const* d_in, const int* in_sizes, int n_in,
                              void* d_out, int out_size) {
    const float* features = (const float*)d_in[0];
    int n = in_sizes[0] / DIM;        // 8192
    int g = in_sizes[1];              // 2048
    int cr = n / g;                   // 4 crops per group (uniform)

    k_normalize<<<n / 8, 256>>>(features, n);
    dim3 grid_b(n / BM, JCHUNKS);
    k_scores<<<grid_b, 256>>>(n);
    k_rowloss<<<n / 8, 256>>>(n, cr);
    k_reduce<<<1, 256>>>((float*)d_out, n);
}

// round 3
// speedup vs baseline: 8.3440x; 8.3440x over previous
#include <cuda_runtime.h>
#include <cuda_bf16.h>
#include <math.h>
#include <stdint.h>

// Problem constants (reference: G=2048, CROPS=4, D=128 -> N=8192)
#define N_ROWS 8192
#define DIM    128
#define NJ     2                      // j-chunks across grid.y
#define TM     128                    // i-tile
#define TN     128                    // j-tile
#define NT     ((N_ROWS / NJ) / TN)   // 32 j-tiles per CTA

#define EXP2_SCALE 2.8853900817779268f   // 1/(tau*ln2), tau=0.5
#define EXP_SELF   7.38905609893065f     // exp(1/tau) = e^2

// Scratch (device globals; no allocation anywhere)
__device__ float          g_z[N_ROWS * DIM];      // fp32 normalized
__device__ __nv_bfloat16  g_zb[N_ROWS * DIM];     // bf16 normalized
__device__ float          g_Spart[NJ][N_ROWS];    // partial full-row exp sums
__device__ float          g_part[N_ROWS / 8];     // per-CTA partial losses

// ---------------------------------------------------------------------------
// helpers
// ---------------------------------------------------------------------------
static __device__ __forceinline__ uint32_t smem_u32(const void* p) {
    uint32_t a;
    asm("{ .reg .u64 t; cvta.to.shared.u64 t, %1; cvt.u32.u64 %0, t; }"
        : "=r"(a) : "l"(p));
    return a;
}

#define LDSM_X4(r0, r1, r2, r3, addr)                                          \
    asm volatile("ldmatrix.sync.aligned.m8n8.x4.shared.b16 {%0,%1,%2,%3}, [%4];" \
                 : "=r"(r0), "=r"(r1), "=r"(r2), "=r"(r3) : "r"(addr))

#define MMA16816(d, a, b0, b1)                                                 \
    asm volatile("mma.sync.aligned.m16n8k16.row.col.f32.bf16.bf16.f32 "        \
                 "{%0,%1,%2,%3},{%4,%5,%6,%7},{%8,%9},{%0,%1,%2,%3};"          \
                 : "+f"((d)[0]), "+f"((d)[1]), "+f"((d)[2]), "+f"((d)[3])      \
                 : "r"((a)[0]), "r"((a)[1]), "r"((a)[2]), "r"((a)[3]),         \
                   "r"(b0), "r"(b1))

#define CP_ASYNC16(dst, src)                                                   \
    asm volatile("cp.async.cg.shared.global [%0], [%1], 16;"                   \
                 :: "r"(dst), "l"(src) : "memory")
#define CP_COMMIT() asm volatile("cp.async.commit_group;" ::: "memory")
#define CP_WAIT(N)  asm volatile("cp.async.wait_group %0;" :: "n"(N) : "memory")

static __device__ __forceinline__ float ex2_fast(float x) {
    float y;
    asm("ex2.approx.ftz.f32 %0, %1;" : "=f"(y) : "f"(x));
    return y;
}

// Swizzled tile layout (128 rows x 16 chunks of 16B, conflict-free ldmatrix):
// off(r,c) = (c>>3)*16384 + r*128 + ((c&7)^(r&7))*16
static __device__ __forceinline__ uint32_t tile_off(int r, int c) {
    return ((uint32_t)(c >> 3) << 14) + ((uint32_t)r << 7)
         + ((uint32_t)((c & 7) ^ (r & 7)) << 4);
}

// async-copy one 128x128 bf16 tile (rows r0..r0+127) into swizzled smem
static __device__ __forceinline__ void cp_tile(uint32_t dst, int r0, int tid) {
    const char* src = (const char*)g_zb + (size_t)r0 * 256;
    #pragma unroll
    for (int it = 0; it < 8; it++) {
        int idx = tid + it * 256;       // 2048 chunks of 16B
        int r = idx >> 4;
        int c = idx & 15;
        CP_ASYNC16(dst + tile_off(r, c), src + (size_t)r * 256 + c * 16);
    }
}

// ---------------------------------------------------------------------------
// Kernel A: row-normalize; write fp32 + bf16 copies (one warp per row)
// ---------------------------------------------------------------------------
__global__ void k_normalize(const float* __restrict__ f, int n) {
    int warp = (blockIdx.x * blockDim.x + threadIdx.x) >> 5;
    int lane = threadIdx.x & 31;
    if (warp >= n) return;
    const float* row = f + (size_t)warp * DIM;
    float v0 = row[lane], v1 = row[lane + 32], v2 = row[lane + 64], v3 = row[lane + 96];
    float ss = v0 * v0 + v1 * v1 + v2 * v2 + v3 * v3;
    #pragma unroll
    for (int o = 16; o; o >>= 1) ss += __shfl_xor_sync(0xffffffffu, ss, o);
    float inv = 1.0f / fmaxf(sqrtf(ss), 1e-8f);
    float z0 = v0 * inv, z1 = v1 * inv, z2 = v2 * inv, z3 = v3 * inv;
    float* z = g_z + (size_t)warp * DIM;
    z[lane] = z0; z[lane + 32] = z1; z[lane + 64] = z2; z[lane + 96] = z3;
    __nv_bfloat16* zb = g_zb + (size_t)warp * DIM;
    zb[lane]      = __float2bfloat16(z0);
    zb[lane + 32] = __float2bfloat16(z1);
    zb[lane + 64] = __float2bfloat16(z2);
    zb[lane + 96] = __float2bfloat16(z3);
}

// ---------------------------------------------------------------------------
// Kernel B: HMMA (mma.sync bf16) GEMM -> ex2 -> row-sum partials.
// 256 threads = 8 warps: warpM = w&3 (32 rows), warpN = w>>2 (64 cols).
// A tile fragments live in registers for the whole CTA; B double-buffered.
// ---------------------------------------------------------------------------
__global__ void __launch_bounds__(256, 1)
k_scores_mma(int n) {
    extern __shared__ __align__(1024) char smem[];
    const uint32_t Abase = smem_u32(smem);
    const uint32_t Bbase0 = Abase + 32768;
    const uint32_t Bbase1 = Abase + 65536;

    const int tid   = threadIdx.x;
    const int lane  = tid & 31;
    const int w     = tid >> 5;
    const int warpM = w & 3;
    const int warpN = w >> 2;

    const int i0 = blockIdx.x * TM;
    const int j0 = blockIdx.y * (n / NJ);

    // Prologue: async-load A and B0 (group0), B1 (group1)
    cp_tile(Abase, i0, tid);
    cp_tile(Bbase0, j0, tid);
    CP_COMMIT();
    cp_tile(Bbase1, j0 + TN, tid);
    CP_COMMIT();
    CP_WAIT(1);            // A + B0 resident
    __syncthreads();

    // Load all A fragments into registers: 2 m-blocks x 8 k-steps x 4 regs
    uint32_t afrag[2][8][4];
    {
        const int aRow = warpM * 32 + (lane & 15);
        const int aSel = lane >> 4;
        #pragma unroll
        for (int mb = 0; mb < 2; mb++)
            #pragma unroll
            for (int ks = 0; ks < 8; ks++) {
                uint32_t addr = Abase + tile_off(aRow + mb * 16, ks * 2 + aSel);
                LDSM_X4(afrag[mb][ks][0], afrag[mb][ks][1],
                        afrag[mb][ks][2], afrag[mb][ks][3], addr);
            }
    }

    // B ldmatrix lane address components
    const int bRow = (lane & 7) + ((lane >> 4) & 1) * 8;   // within 16-row group
    const int bSel = (lane >> 3) & 1;                       // k-chunk bit

    float rs[2][2] = {{0.f, 0.f}, {0.f, 0.f}};   // row sums: [mb][row / row+8]

    for (int t = 0; t < NT; t++) {
        const uint32_t Bb = (t & 1) ? Bbase1 : Bbase0;

        float acc[2][8][4];
        #pragma unroll
        for (int mb = 0; mb < 2; mb++)
            #pragma unroll
            for (int nb = 0; nb < 8; nb++)
                #pragma unroll
                for (int q = 0; q < 4; q++) acc[mb][nb][q] = 0.0f;

        #pragma unroll
        for (int ks = 0; ks < 8; ks++) {
            #pragma unroll
            for (int nb2 = 0; nb2 < 4; nb2++) {
                uint32_t b0, b1, b2, b3;
                uint32_t addr = Bb + tile_off(warpN * 64 + nb2 * 16 + bRow,
                                              ks * 2 + bSel);
                LDSM_X4(b0, b1, b2, b3, addr);
                #pragma unroll
                for (int mb = 0; mb < 2; mb++) {
                    MMA16816(acc[mb][nb2 * 2],     afrag[mb][ks], b0, b1);
                    MMA16816(acc[mb][nb2 * 2 + 1], afrag[mb][ks], b2, b3);
                }
            }
        }

        // epilogue: exp2(scale * s) and row-sum accumulate
        #pragma unroll
        for (int mb = 0; mb < 2; mb++) {
            float s0 = 0.f, s1 = 0.f;
            #pragma unroll
            for (int nb = 0; nb < 8; nb++) {
                s0 += ex2_fast(acc[mb][nb][0] * EXP2_SCALE)
                    + ex2_fast(acc[mb][nb][1] * EXP2_SCALE);
                s1 += ex2_fast(acc[mb][nb][2] * EXP2_SCALE)
                    + ex2_fast(acc[mb][nb][3] * EXP2_SCALE);
            }
            rs[mb][0] += s0;
            rs[mb][1] += s1;
        }

        // pipeline: refill the buffer we just finished reading
        __syncthreads();
        if (t + 1 < NT) {
            if (t + 2 < NT) {
                cp_tile(Bb, j0 + (t + 2) * TN, tid);
                CP_COMMIT();
                CP_WAIT(1);        // B_{t+1} complete, B_{t+2} in flight
            } else {
                CP_WAIT(0);        // last tile: everything complete
            }
            __syncthreads();
        }
    }

    // reduce across the 4 lanes of each row-quad (deterministic order)
    #pragma unroll
    for (int mb = 0; mb < 2; mb++)
        #pragma unroll
        for (int h = 0; h < 2; h++) {
            rs[mb][h] += __shfl_xor_sync(0xffffffffu, rs[mb][h], 1);
            rs[mb][h] += __shfl_xor_sync(0xffffffffu, rs[mb][h], 2);
        }

    __syncthreads();
    float* red = (float*)smem;   // 128 rows x 2 warpN halves
    if ((lane & 3) == 0) {
        int g = lane >> 2;
        #pragma unroll
        for (int mb = 0; mb < 2; mb++)
            #pragma unroll
            for (int h = 0; h < 2; h++)
                red[(warpM * 32 + mb * 16 + h * 8 + g) * 2 + warpN] = rs[mb][h];
    }
    __syncthreads();
    if (tid < TM)
        g_Spart[blockIdx.y][i0 + tid] = red[tid * 2] + red[tid * 2 + 1];
}

// ---------------------------------------------------------------------------
// Kernel C: fp32 pos per row + per-row loss + per-CTA partial sums
// ---------------------------------------------------------------------------
__global__ void k_rowloss(int n, int cr) {
    __shared__ float tvals[8];
    int row  = blockIdx.x * 8 + (threadIdx.x >> 5);
    int lane = threadIdx.x & 31;
    float tv = 0.0f;
    if (row < n) {
        const float* zr = g_z + (size_t)row * DIM;
        float a0 = zr[lane], a1 = zr[lane + 32], a2 = zr[lane + 64], a3 = zr[lane + 96];
        int gb = (row / cr) * cr;
        float P = 0.0f;
        for (int jj = 0; jj < cr; jj++) {
            const float* zc = g_z + (size_t)(gb + jj) * DIM;
            float d = a0 * zc[lane] + a1 * zc[lane + 32] + a2 * zc[lane + 64] + a3 * zc[lane + 96];
            #pragma unroll
            for (int o = 16; o; o >>= 1) d += __shfl_xor_sync(0xffffffffu, d, o);
            P += exp2f(d * EXP2_SCALE);
        }
        float S = 0.0f;
        #pragma unroll
        for (int c = 0; c < NJ; c++) S += g_Spart[c][row];
        float pos = P - EXP_SELF;
        float neg = S - P;
        tv = logf(neg) - logf(pos);
    }
    if (lane == 0) tvals[threadIdx.x >> 5] = tv;
    __syncthreads();
    if (threadIdx.x == 0) {
        float s = 0.0f;
        #pragma unroll
        for (int u = 0; u < 8; u++) s += tvals[u];
        g_part[blockIdx.x] = s;
    }
}

// ---------------------------------------------------------------------------
// Kernel D: deterministic final reduction -> mean
// ---------------------------------------------------------------------------
__global__ void k_reduce(float* __restrict__ out, int n) {
    __shared__ float sm[256];
    int t = threadIdx.x;
    int m = n / 8;
    float s = 0.0f;
    for (int idx = t; idx < m; idx += 256) s += g_part[idx];
    sm[t] = s;
    __syncthreads();
    #pragma unroll
    for (int off = 128; off; off >>= 1) {
        if (t < off) sm[t] += sm[t + off];
        __syncthreads();
    }
    if (t == 0) out[0] = sm[0] / (float)n;
}

// ---------------------------------------------------------------------------
extern "C" void kernel_launch(void* const* d_in, const int* in_sizes, int n_in,
                              void* d_out, int out_size) {
    const float* features = (const float*)d_in[0];
    int n  = in_sizes[0] / DIM;   // 8192
    int g  = in_sizes[1];         // 2048
    int cr = n / g;               // 4

    const int SMEM_DYN = 3 * 32768;   // A + B0 + B1
    cudaFuncSetAttribute(k_scores_mma,
                         cudaFuncAttributeMaxDynamicSharedMemorySize, SMEM_DYN);

    k_normalize<<<n / 8, 256>>>(features, n);
    dim3 grid_b(n / TM, NJ);
    k_scores_mma<<<grid_b, 256, SMEM_DYN>>>(n);
    k_rowloss<<<n / 8, 256>>>(n, cr);
    k_reduce<<<1, 256>>>((float*)d_out, n);
}

// round 4
// speedup vs baseline: 12.2009x; 1.4622x over previous
#include <cuda_runtime.h>
#include <cuda_bf16.h>
#include <math.h>
#include <stdint.h>

// Problem constants (reference: G=2048, CROPS=4, D=128 -> N=8192)
#define N_ROWS 8192
#define DIM    128
#define NP     (N_ROWS / 128)            // 64 row panels

#define EXP2_SCALE 2.8853900817779268f   // 1/(tau*ln2), tau=0.5
#define SQRT_E2S   1.6986436f            // sqrt(EXP2_SCALE), folded into bf16 z
#define EXP_SELF   7.38905609893065f     // exp(1/tau) = e^2

// Scratch (device globals; no allocation anywhere)
__device__ float          g_z[N_ROWS * DIM];        // fp32 normalized (unscaled)
__device__ __nv_bfloat16  g_zb[N_ROWS * DIM];       // bf16 normalized * sqrt(scale)
__device__ float          g_P[NP * NP * 128];       // per-(panel,slot) partial sums
__device__ float          g_part[N_ROWS / 8];       // per-CTA partial losses

// ---------------------------------------------------------------------------
// helpers
// ---------------------------------------------------------------------------
static __device__ __forceinline__ uint32_t smem_u32(const void* p) {
    uint32_t a;
    asm("{ .reg .u64 t; cvta.to.shared.u64 t, %1; cvt.u32.u64 %0, t; }"
        : "=r"(a) : "l"(p));
    return a;
}

#define LDSM_X4(r0, r1, r2, r3, addr)                                          \
    asm volatile("ldmatrix.sync.aligned.m8n8.x4.shared.b16 {%0,%1,%2,%3}, [%4];" \
                 : "=r"(r0), "=r"(r1), "=r"(r2), "=r"(r3) : "r"(addr))

#define MMA16816(d, a, b0, b1)                                                 \
    asm volatile("mma.sync.aligned.m16n8k16.row.col.f32.bf16.bf16.f32 "        \
                 "{%0,%1,%2,%3},{%4,%5,%6,%7},{%8,%9},{%0,%1,%2,%3};"          \
                 : "+f"((d)[0]), "+f"((d)[1]), "+f"((d)[2]), "+f"((d)[3])      \
                 : "r"((a)[0]), "r"((a)[1]), "r"((a)[2]), "r"((a)[3]),         \
                   "r"(b0), "r"(b1))

#define CP_ASYNC16(dst, src)                                                   \
    asm volatile("cp.async.cg.shared.global [%0], [%1], 16;"                   \
                 :: "r"(dst), "l"(src) : "memory")
#define CP_COMMIT() asm volatile("cp.async.commit_group;" ::: "memory")
#define CP_WAIT(N)  asm volatile("cp.async.wait_group %0;" :: "n"(N) : "memory")

static __device__ __forceinline__ float ex2_fast(float x) {
    float y;
    asm("ex2.approx.ftz.f32 %0, %1;" : "=f"(y) : "f"(x));
    return y;
}

// Swizzled tile layout (128 rows x 16 chunks of 16B, conflict-free ldmatrix):
// off(r,c) = (c>>3)*16384 + r*128 + ((c&7)^(r&7))*16
static __device__ __forceinline__ uint32_t tile_off(int r, int c) {
    return ((uint32_t)(c >> 3) << 14) + ((uint32_t)r << 7)
         + ((uint32_t)((c & 7) ^ (r & 7)) << 4);
}

// async-copy one 128x128 bf16 panel (rows r0..r0+127) into swizzled smem
static __device__ __forceinline__ void cp_tile(uint32_t dst, int r0, int tid) {
    const char* src = (const char*)g_zb + (size_t)r0 * 256;
    #pragma unroll
    for (int it = 0; it < 8; it++) {
        int idx = tid + it * 256;       // 2048 chunks of 16B
        int r = idx >> 4;
        int c = idx & 15;
        CP_ASYNC16(dst + tile_off(r, c), src + (size_t)r * 256 + c * 16);
    }
}

// ---------------------------------------------------------------------------
// Kernel A: row-normalize; fp32 copy + bf16 copy pre-scaled by sqrt(EXP2_SCALE)
// ---------------------------------------------------------------------------
__global__ void k_normalize(const float* __restrict__ f, int n) {
    int warp = (blockIdx.x * blockDim.x + threadIdx.x) >> 5;
    int lane = threadIdx.x & 31;
    if (warp >= n) return;
    const float* row = f + (size_t)warp * DIM;
    float v0 = row[lane], v1 = row[lane + 32], v2 = row[lane + 64], v3 = row[lane + 96];
    float ss = v0 * v0 + v1 * v1 + v2 * v2 + v3 * v3;
    #pragma unroll
    for (int o = 16; o; o >>= 1) ss += __shfl_xor_sync(0xffffffffu, ss, o);
    float inv = 1.0f / fmaxf(sqrtf(ss), 1e-8f);
    float z0 = v0 * inv, z1 = v1 * inv, z2 = v2 * inv, z3 = v3 * inv;
    float* z = g_z + (size_t)warp * DIM;
    z[lane] = z0; z[lane + 32] = z1; z[lane + 64] = z2; z[lane + 96] = z3;
    __nv_bfloat16* zb = g_zb + (size_t)warp * DIM;
    zb[lane]      = __float2bfloat16(z0 * SQRT_E2S);
    zb[lane + 32] = __float2bfloat16(z1 * SQRT_E2S);
    zb[lane + 64] = __float2bfloat16(z2 * SQRT_E2S);
    zb[lane + 96] = __float2bfloat16(z3 * SQRT_E2S);
}

// ---------------------------------------------------------------------------
// Kernel B: symmetric-tile HMMA. grid (NP, NP); lower triangle exits.
// Tile (I,J): E-tile = exp2(Zb[I] @ Zb[J]^T); write row sums -> g_P[I][J][*]
// and (I!=J) col sums -> g_P[J][I][*]. 8 warps: warpM=w&3, warpN=w>>2.
// ---------------------------------------------------------------------------
__global__ void __launch_bounds__(256, 2)
k_scores_sym() {
    const int I = blockIdx.x;
    const int J = blockIdx.y;
    if (J < I) return;

    extern __shared__ __align__(1024) char smem[];
    __shared__ float red[128][2];      // row sums: [row][warpN]
    __shared__ float colred[128][4];   // col sums: [col][warpM]

    const uint32_t Abase = smem_u32(smem);
    const uint32_t Bbase = Abase + 32768;

    const int tid   = threadIdx.x;
    const int lane  = tid & 31;
    const int w     = tid >> 5;
    const int warpM = w & 3;
    const int warpN = w >> 2;

    cp_tile(Abase, I * 128, tid);
    cp_tile(Bbase, J * 128, tid);
    CP_COMMIT();
    CP_WAIT(0);
    __syncthreads();

    const int aRow = warpM * 32 + (lane & 15);
    const int aSel = lane >> 4;
    const int bRow = (lane & 7) + ((lane >> 4) & 1) * 8;
    const int bSel = (lane >> 3) & 1;

    float acc[2][8][4];
    #pragma unroll
    for (int mb = 0; mb < 2; mb++)
        #pragma unroll
        for (int nb = 0; nb < 8; nb++)
            #pragma unroll
            for (int q = 0; q < 4; q++) acc[mb][nb][q] = 0.0f;

    #pragma unroll
    for (int ks = 0; ks < 8; ks++) {
        uint32_t af[2][4];
        #pragma unroll
        for (int mb = 0; mb < 2; mb++)
            LDSM_X4(af[mb][0], af[mb][1], af[mb][2], af[mb][3],
                    Abase + tile_off(aRow + mb * 16, ks * 2 + aSel));
        #pragma unroll
        for (int nb2 = 0; nb2 < 4; nb2++) {
            uint32_t b0, b1, b2, b3;
            LDSM_X4(b0, b1, b2, b3,
                    Bbase + tile_off(warpN * 64 + nb2 * 16 + bRow, ks * 2 + bSel));
            #pragma unroll
            for (int mb = 0; mb < 2; mb++) {
                MMA16816(acc[mb][nb2 * 2],     af[mb], b0, b1);
                MMA16816(acc[mb][nb2 * 2 + 1], af[mb], b2, b3);
            }
        }
    }

    // Epilogue: exp2 once per element; accumulate row sums + col sums
    float rs[2][2] = {{0.f, 0.f}, {0.f, 0.f}};
    float cs[16];
    #pragma unroll
    for (int k = 0; k < 16; k++) cs[k] = 0.f;

    #pragma unroll
    for (int mb = 0; mb < 2; mb++)
        #pragma unroll
        for (int nb = 0; nb < 8; nb++)
            #pragma unroll
            for (int q = 0; q < 4; q++) {
                float e = ex2_fast(acc[mb][nb][q]);   // operands pre-scaled
                rs[mb][q >> 1]      += e;
                cs[nb * 2 + (q & 1)] += e;
            }

    // row reduce across lane&3 (cols)
    #pragma unroll
    for (int mb = 0; mb < 2; mb++)
        #pragma unroll
        for (int h = 0; h < 2; h++) {
            rs[mb][h] += __shfl_xor_sync(0xffffffffu, rs[mb][h], 1);
            rs[mb][h] += __shfl_xor_sync(0xffffffffu, rs[mb][h], 2);
        }
    // col reduce across lane>>2 (rows)
    #pragma unroll
    for (int k = 0; k < 16; k++) {
        cs[k] += __shfl_xor_sync(0xffffffffu, cs[k], 4);
        cs[k] += __shfl_xor_sync(0xffffffffu, cs[k], 8);
        cs[k] += __shfl_xor_sync(0xffffffffu, cs[k], 16);
    }

    if ((lane & 3) == 0) {
        int gq = lane >> 2;
        #pragma unroll
        for (int mb = 0; mb < 2; mb++)
            #pragma unroll
            for (int h = 0; h < 2; h++)
                red[warpM * 32 + mb * 16 + h * 8 + gq][warpN] = rs[mb][h];
    }
    if (lane < 4) {
        #pragma unroll
        for (int k = 0; k < 16; k++)
            colred[warpN * 64 + (k >> 1) * 8 + lane * 2 + (k & 1)][warpM] = cs[k];
    }
    __syncthreads();

    if (tid < 128) {
        float r = red[tid][0] + red[tid][1];
        g_P[((size_t)I * NP + J) * 128 + tid] = r;
        if (I != J) {
            float c = colred[tid][0] + colred[tid][1] + colred[tid][2] + colred[tid][3];
            g_P[((size_t)J * NP + I) * 128 + tid] = c;
        }
    }
}

// ---------------------------------------------------------------------------
// Kernel C: gather S from g_P slots + fp32 pos + per-row loss + CTA partials
// ---------------------------------------------------------------------------
__global__ void k_rowloss(int n, int cr) {
    __shared__ float tvals[8];
    int row  = blockIdx.x * 8 + (threadIdx.x >> 5);
    int lane = threadIdx.x & 31;
    float tv = 0.0f;
    if (row < n) {
        const float* zr = g_z + (size_t)row * DIM;
        float a0 = zr[lane], a1 = zr[lane + 32], a2 = zr[lane + 64], a3 = zr[lane + 96];
        int gb = (row / cr) * cr;
        float P = 0.0f;
        for (int jj = 0; jj < cr; jj++) {
            const float* zc = g_z + (size_t)(gb + jj) * DIM;
            float d = a0 * zc[lane] + a1 * zc[lane + 32] + a2 * zc[lane + 64] + a3 * zc[lane + 96];
            #pragma unroll
            for (int o = 16; o; o >>= 1) d += __shfl_xor_sync(0xffffffffu, d, o);
            P += exp2f(d * EXP2_SCALE);
        }
        // gather full-row sum S from the 64 panel slots (fixed order)
        int Ip   = row >> 7;
        int r127 = row & 127;
        const float* pbase = g_P + (size_t)Ip * NP * 128 + r127;
        float s = pbase[(size_t)lane * 128] + pbase[(size_t)(lane + 32) * 128];
        #pragma unroll
        for (int o = 16; o; o >>= 1) s += __shfl_xor_sync(0xffffffffu, s, o);

        float pos = P - EXP_SELF;
        float neg = s - P;
        tv = logf(neg) - logf(pos);
    }
    if (lane == 0) tvals[threadIdx.x >> 5] = tv;
    __syncthreads();
    if (threadIdx.x == 0) {
        float acc = 0.0f;
        #pragma unroll
        for (int u = 0; u < 8; u++) acc += tvals[u];
        g_part[blockIdx.x] = acc;
    }
}

// ---------------------------------------------------------------------------
// Kernel D: deterministic final reduction -> mean
// ---------------------------------------------------------------------------
__global__ void k_reduce(float* __restrict__ out, int n) {
    __shared__ float sm[256];
    int t = threadIdx.x;
    int m = n / 8;
    float s = 0.0f;
    for (int idx = t; idx < m; idx += 256) s += g_part[idx];
    sm[t] = s;
    __syncthreads();
    #pragma unroll
    for (int off = 128; off; off >>= 1) {
        if (t < off) sm[t] += sm[t + off];
        __syncthreads();
    }
    if (t == 0) out[0] = sm[0] / (float)n;
}

// ---------------------------------------------------------------------------
extern "C" void kernel_launch(void* const* d_in, const int* in_sizes, int n_in,
                              void* d_out, int out_size) {
    const float* features = (const float*)d_in[0];
    int n  = in_sizes[0] / DIM;   // 8192
    int g  = in_sizes[1];         // 2048
    int cr = n / g;               // 4

    const int SMEM_DYN = 2 * 32768;   // A panel + B panel
    cudaFuncSetAttribute(k_scores_sym,
                         cudaFuncAttributeMaxDynamicSharedMemorySize, SMEM_DYN);

    k_normalize<<<n / 8, 256>>>(features, n);
    dim3 grid_b(NP, NP);
    k_scores_sym<<<grid_b, 256, SMEM_DYN>>>();
    k_rowloss<<<n / 8, 256>>>(n, cr);
    k_reduce<<<1, 256>>>((float*)d_out, n);
}